// round 2
// baseline (speedup 1.0000x reference)
#include <cuda_runtime.h>

#define NN 50000
#define EE 800000
#define ET (EE + NN)
#define FF 128
#define SLOPE 0.2f
#define EPSBN 1e-5f

// ---------------- scratch (device globals: no allocations allowed) ----------
__device__ __align__(16) float g_h[NN * FF];    // post-GEMM features
__device__ __align__(16) float g_act[NN * FF];  // layer activations
__device__ __align__(16) float g_agg[NN * FF];  // attention aggregation
__device__ __align__(16) float g_den[NN * 2];   // softmax denominators
__device__ __align__(16) float g_als[NN * 2];   // src logits per head
__device__ __align__(16) float g_ald[NN * 2];   // dst logits per head
__device__ __align__(16) float g_sum[FF];       // BN channel sums
__device__ __align__(16) float g_sq[FF];        // BN channel sum sq
__device__ int g_is64;                          // edge_index dtype flag

// ---------------- dtype detection: int64 vs int32 edge_index ----------------
// For int64 layout (values in [0,50000)), every odd 32-bit word is 0.
// For int32 layout, odd words are random node ids; OR over 2048 is ~never 0.
__global__ void k_detect(const int* __restrict__ ei32) {
    int acc = 0;
    for (int i = threadIdx.x; i < 2048; i += 32) acc |= ei32[2 * i + 1];
#pragma unroll
    for (int off = 16; off; off >>= 1)
        acc |= __shfl_xor_sync(0xffffffffu, acc, off);
    if (threadIdx.x == 0) g_is64 = (acc == 0) ? 1 : 0;
}

// ---------------- GEMM: g_h[n,128] = A[n,128] @ W[128,128] ------------------
#define GEMM_SMEM ((128 * 128 + 128 * 36) * 4)

__global__ void __launch_bounds__(256) k_gemm(const float* __restrict__ A,
                                              const float* __restrict__ W) {
    extern __shared__ float smem[];
    float* Ws = smem;                 // [128][128]
    float* As = smem + 128 * 128;     // [128][36] transposed

    const float* Ap = A ? A : g_act;
    int t = threadIdx.x;
    int n0 = blockIdx.x * 32;

    {
        const float4* W4 = (const float4*)W;
        float4* Ws4 = (float4*)Ws;
#pragma unroll
        for (int i = 0; i < 16; i++) Ws4[t + i * 256] = W4[t + i * 256];
    }
    {
        int r = t >> 3;              // 0..31
        int cb = (t & 7) * 16;       // 0..112
        int row = n0 + r;
        if (row < NN) {
#pragma unroll
            for (int j = 0; j < 16; j++)
                As[(cb + j) * 36 + r] = Ap[row * 128 + cb + j];
        } else {
#pragma unroll
            for (int j = 0; j < 16; j++) As[(cb + j) * 36 + r] = 0.f;
        }
    }
    __syncthreads();

    int tr = t >> 5, tc = t & 31;
    int r0 = tr * 4, c0 = tc * 4;

    float acc[4][4];
#pragma unroll
    for (int i = 0; i < 4; i++)
#pragma unroll
        for (int j = 0; j < 4; j++) acc[i][j] = 0.f;

#pragma unroll 4
    for (int k = 0; k < 128; k++) {
        float4 a = *(const float4*)&As[k * 36 + r0];
        float4 b = *(const float4*)&Ws[k * 128 + c0];
        acc[0][0] += a.x * b.x; acc[0][1] += a.x * b.y; acc[0][2] += a.x * b.z; acc[0][3] += a.x * b.w;
        acc[1][0] += a.y * b.x; acc[1][1] += a.y * b.y; acc[1][2] += a.y * b.z; acc[1][3] += a.y * b.w;
        acc[2][0] += a.z * b.x; acc[2][1] += a.z * b.y; acc[2][2] += a.z * b.z; acc[2][3] += a.z * b.w;
        acc[3][0] += a.w * b.x; acc[3][1] += a.w * b.y; acc[3][2] += a.w * b.z; acc[3][3] += a.w * b.w;
    }

#pragma unroll
    for (int i = 0; i < 4; i++) {
        int row = n0 + r0 + i;
        if (row < NN)
            *(float4*)&g_h[row * 128 + c0] =
                make_float4(acc[i][0], acc[i][1], acc[i][2], acc[i][3]);
    }
}

// ---------------- per-node prep: logits + zero agg/den ----------------------
__global__ void k_prep(const float* __restrict__ asrc,
                       const float* __restrict__ adst) {
    int w = (blockIdx.x * blockDim.x + threadIdx.x) >> 5;
    int lane = threadIdx.x & 31;
    if (w >= NN) return;

    float4 hv = *(const float4*)&g_h[w * 128 + lane * 4];
    float4 s4 = *(const float4*)&asrc[lane * 4];
    float4 d4 = *(const float4*)&adst[lane * 4];
    float ps = hv.x * s4.x + hv.y * s4.y + hv.z * s4.z + hv.w * s4.w;
    float pd = hv.x * d4.x + hv.y * d4.y + hv.z * d4.z + hv.w * d4.w;
#pragma unroll
    for (int off = 8; off; off >>= 1) {
        ps += __shfl_xor_sync(0xffffffffu, ps, off);
        pd += __shfl_xor_sync(0xffffffffu, pd, off);
    }
    *(float4*)&g_agg[w * 128 + lane * 4] = make_float4(0.f, 0.f, 0.f, 0.f);
    if (lane == 0)  { g_als[w * 2]     = ps; g_ald[w * 2]     = pd; g_den[w * 2]     = 0.f; }
    if (lane == 16) { g_als[w * 2 + 1] = ps; g_ald[w * 2 + 1] = pd; g_den[w * 2 + 1] = 0.f; }
}

// ---------------- edge pass: one warp per edge (incl. self loops) ------------
__global__ void k_edge(const void* __restrict__ ei) {
    int w = (int)(((long long)blockIdx.x * blockDim.x + threadIdx.x) >> 5);
    int lane = threadIdx.x & 31;
    if (w >= ET) return;

    int s, d;
    if (w < EE) {
        if (g_is64) {
            const long long* e64 = (const long long*)ei;
            s = (int)e64[w]; d = (int)e64[EE + w];
        } else {
            const int* e32 = (const int*)ei;
            s = e32[w]; d = e32[EE + w];
        }
        s = min(max(s, 0), NN - 1);
        d = min(max(d, 0), NN - 1);
    } else {
        s = d = w - EE;
    }

    int hd = lane >> 4;
    float e = g_als[s * 2 + hd] + g_ald[d * 2 + hd];
    e = (e > 0.f) ? e : SLOPE * e;
    float wg = __expf(e);   // max-subtraction cancels analytically in alpha

    float4 hv = *(const float4*)&g_h[s * 128 + lane * 4];
    float* p = &g_agg[d * 128 + lane * 4];
    asm volatile("red.global.add.v4.f32 [%0], {%1,%2,%3,%4};"
                 :: "l"(p), "f"(hv.x * wg), "f"(hv.y * wg),
                    "f"(hv.z * wg), "f"(hv.w * wg)
                 : "memory");
    if ((lane & 15) == 0) atomicAdd(&g_den[d * 2 + hd], wg);
}

// ---------------- zero BN stats ----------------------------------------------
__global__ void k_zstat() {
    int t = threadIdx.x;
    if (t < FF) { g_sum[t] = 0.f; g_sq[t] = 0.f; }
}

// ---------------- finalize: act = agg/den + b ; accumulate BN stats ----------
__global__ void k_fin(const float* __restrict__ b) {
    __shared__ float ssum[FF], ssq[FF];
    int t = threadIdx.x;
    if (t < FF) { ssum[t] = 0.f; ssq[t] = 0.f; }
    __syncthreads();

    int lane = t & 31;
    int node = blockIdx.x * 8 + (t >> 5);
    int c = lane * 4;
    float v0 = 0.f, v1 = 0.f, v2 = 0.f, v3 = 0.f;
    if (node < NN) {
        int hd = lane >> 4;
        float inv = 1.f / (g_den[node * 2 + hd] + 1e-16f);
        float4 a = *(const float4*)&g_agg[node * 128 + c];
        float4 bb = *(const float4*)&b[c];
        v0 = a.x * inv + bb.x;
        v1 = a.y * inv + bb.y;
        v2 = a.z * inv + bb.z;
        v3 = a.w * inv + bb.w;
        *(float4*)&g_act[node * 128 + c] = make_float4(v0, v1, v2, v3);
    }
    atomicAdd(&ssum[c + 0], v0); atomicAdd(&ssq[c + 0], v0 * v0);
    atomicAdd(&ssum[c + 1], v1); atomicAdd(&ssq[c + 1], v1 * v1);
    atomicAdd(&ssum[c + 2], v2); atomicAdd(&ssq[c + 2], v2 * v2);
    atomicAdd(&ssum[c + 3], v3); atomicAdd(&ssq[c + 3], v3 * v3);
    __syncthreads();
    if (t < FF) { atomicAdd(&g_sum[t], ssum[t]); atomicAdd(&g_sq[t], ssq[t]); }
}

// ---------------- batchnorm + relu (in place on g_act) -----------------------
__global__ void k_bn(const float* __restrict__ g, const float* __restrict__ be) {
    int i = blockIdx.x * blockDim.x + threadIdx.x;     // float4 index
    if (i >= NN * 32) return;
    int c = (i & 31) * 4;
    const float invn = 1.f / (float)NN;
    float4 v  = *(const float4*)&g_act[i * 4];
    float4 s  = *(const float4*)&g_sum[c];
    float4 q  = *(const float4*)&g_sq[c];
    float4 gg = *(const float4*)&g[c];
    float4 bb = *(const float4*)&be[c];

    float mu, var, y;
    mu = s.x * invn; var = q.x * invn - mu * mu;
    y = (v.x - mu) * rsqrtf(var + EPSBN) * gg.x + bb.x; v.x = fmaxf(y, 0.f);
    mu = s.y * invn; var = q.y * invn - mu * mu;
    y = (v.y - mu) * rsqrtf(var + EPSBN) * gg.y + bb.y; v.y = fmaxf(y, 0.f);
    mu = s.z * invn; var = q.z * invn - mu * mu;
    y = (v.z - mu) * rsqrtf(var + EPSBN) * gg.z + bb.z; v.z = fmaxf(y, 0.f);
    mu = s.w * invn; var = q.w * invn - mu * mu;
    y = (v.w - mu) * rsqrtf(var + EPSBN) * gg.w + bb.w; v.w = fmaxf(y, 0.f);

    *(float4*)&g_act[i * 4] = v;
}

// ---------------- output layer: mean over heads + bias ----------------------
__global__ void k_out(const float* __restrict__ b2, float* __restrict__ out) {
    int i = blockIdx.x * blockDim.x + threadIdx.x;     // (node,16 float4s)
    if (i >= NN * 16) return;
    int node = i >> 4;
    int c = (i & 15) * 4;
    float i0 = 1.f / (g_den[node * 2] + 1e-16f);
    float i1 = 1.f / (g_den[node * 2 + 1] + 1e-16f);
    float4 a0 = *(const float4*)&g_agg[node * 128 + c];
    float4 a1 = *(const float4*)&g_agg[node * 128 + 64 + c];
    float4 bb = *(const float4*)&b2[c];
    float4 r;
    r.x = 0.5f * (a0.x * i0 + a1.x * i1) + bb.x;
    r.y = 0.5f * (a0.y * i0 + a1.y * i1) + bb.y;
    r.z = 0.5f * (a0.z * i0 + a1.z * i1) + bb.z;
    r.w = 0.5f * (a0.w * i0 + a1.w * i1) + bb.w;
    *(float4*)&out[node * 64 + c] = r;
}

// ---------------- launch -----------------------------------------------------
extern "C" void kernel_launch(void* const* d_in, const int* in_sizes, int n_in,
                              void* d_out, int out_size) {
    (void)in_sizes; (void)n_in; (void)out_size;
    const float* x      = (const float*)d_in[0];
    const void*  ei     = d_in[1];
    const float* W0  = (const float*)d_in[2];
    const float* as0 = (const float*)d_in[3];
    const float* ad0 = (const float*)d_in[4];
    const float* b0  = (const float*)d_in[5];
    const float* g0  = (const float*)d_in[6];
    const float* be0 = (const float*)d_in[7];
    const float* W1  = (const float*)d_in[8];
    const float* as1 = (const float*)d_in[9];
    const float* ad1 = (const float*)d_in[10];
    const float* b1  = (const float*)d_in[11];
    const float* g1  = (const float*)d_in[12];
    const float* be1 = (const float*)d_in[13];
    const float* W2  = (const float*)d_in[14];
    const float* as2 = (const float*)d_in[15];
    const float* ad2 = (const float*)d_in[16];
    const float* b2  = (const float*)d_in[17];
    float* out = (float*)d_out;

    cudaFuncSetAttribute(k_gemm, cudaFuncAttributeMaxDynamicSharedMemorySize,
                         GEMM_SMEM);

    const int GB   = (NN + 31) / 32;
    const int PB   = (NN * 32 + 255) / 256;
    const int EB   = (int)(((long long)ET * 32 + 255) / 256);
    const int FB   = (NN + 7) / 8;
    const int BNB  = (NN * 32 + 255) / 256;
    const int OB   = (NN * 16 + 255) / 256;

    k_detect<<<1, 32>>>((const int*)ei);

    // ---- layer 0 ----
    k_gemm<<<GB, 256, GEMM_SMEM>>>(x, W0);
    k_prep<<<PB, 256>>>(as0, ad0);
    k_edge<<<EB, 256>>>(ei);
    k_zstat<<<1, 128>>>();
    k_fin<<<FB, 256>>>(b0);
    k_bn<<<BNB, 256>>>(g0, be0);

    // ---- layer 1 ----
    k_gemm<<<GB, 256, GEMM_SMEM>>>(nullptr, W1);
    k_prep<<<PB, 256>>>(as1, ad1);
    k_edge<<<EB, 256>>>(ei);
    k_zstat<<<1, 128>>>();
    k_fin<<<FB, 256>>>(b1);
    k_bn<<<BNB, 256>>>(g1, be1);

    // ---- layer 2 (mean over heads, no BN) ----
    k_gemm<<<GB, 256, GEMM_SMEM>>>(nullptr, W2);
    k_prep<<<PB, 256>>>(as2, ad2);
    k_edge<<<EB, 256>>>(ei);
    k_out<<<OB, 256>>>(b2, out);
}

// round 3
// speedup vs baseline: 1.6062x; 1.6062x over previous
#include <cuda_runtime.h>
#include <cuda_fp16.h>

#define NN 50000
#define EE 800000
#define ET (EE + NN)
#define FF 128
#define SLOPE 0.2f
#define EPSBN 1e-5f

// ---------------- scratch (device globals) -----------------------------------
__device__ __align__(16) __half g_hh[NN * FF];   // post-GEMM features (half)
__device__ __align__(16) float g_act[NN * FF];   // layer activations (fp32)
__device__ __align__(16) float g_als[NN * 2];    // src logits per head
__device__ __align__(16) float g_ald[NN * 2];    // dst logits per head
__device__ __align__(16) float g_sum[FF];        // BN channel sums
__device__ __align__(16) float g_sq[FF];         // BN channel sum sq
__device__ int g_deg[NN];                        // in-degree
__device__ int g_off[NN + 1];                    // CSR offsets
__device__ int g_cur[NN];                        // scatter cursors
__device__ int g_srcs[ET];                       // CSR src lists (by dst)
__device__ int g_is64;                           // edge dtype flag

// ---------------- dtype detection: int64 vs int32 edge_index ----------------
__global__ void k_detect(const int* __restrict__ ei32) {
    int acc = 0;
    for (int i = threadIdx.x; i < 2048; i += 32) acc |= ei32[2 * i + 1];
#pragma unroll
    for (int off = 16; off; off >>= 1)
        acc |= __shfl_xor_sync(0xffffffffu, acc, off);
    if (threadIdx.x == 0) g_is64 = (acc == 0) ? 1 : 0;
}

// ---------------- CSR build --------------------------------------------------
__global__ void k_zdeg() {
    int i = blockIdx.x * blockDim.x + threadIdx.x;
    if (i < NN) g_deg[i] = 0;
}

__device__ __forceinline__ void load_edge(const void* ei, int e, int& s, int& d) {
    if (e < EE) {
        if (g_is64) {
            const long long* e64 = (const long long*)ei;
            s = (int)e64[e]; d = (int)e64[EE + e];
        } else {
            const int* e32 = (const int*)ei;
            s = e32[e]; d = e32[EE + e];
        }
        s = min(max(s, 0), NN - 1);
        d = min(max(d, 0), NN - 1);
    } else {
        s = d = e - EE;
    }
}

__global__ void k_hist(const void* __restrict__ ei) {
    int e = blockIdx.x * blockDim.x + threadIdx.x;
    if (e >= ET) return;
    int s, d; load_edge(ei, e, s, d);
    atomicAdd(&g_deg[d], 1);
}

// single-block exclusive scan over g_deg -> g_off (1024 threads, warp-scan)
__global__ void __launch_bounds__(1024) k_scan() {
    __shared__ int warpsum[32];
    __shared__ int carry;
    int t = threadIdx.x, lane = t & 31, w = t >> 5;
    if (t == 0) carry = 0;
    __syncthreads();
    for (int base = 0; base < NN; base += 1024) {
        int i = base + t;
        int v = (i < NN) ? g_deg[i] : 0;
        int x = v;
#pragma unroll
        for (int off = 1; off < 32; off <<= 1) {
            int y = __shfl_up_sync(0xffffffffu, x, off);
            if (lane >= off) x += y;
        }
        if (lane == 31) warpsum[w] = x;
        __syncthreads();
        if (w == 0) {
            int s = warpsum[lane];
#pragma unroll
            for (int off = 1; off < 32; off <<= 1) {
                int y = __shfl_up_sync(0xffffffffu, s, off);
                if (lane >= off) s += y;
            }
            warpsum[lane] = s;
        }
        __syncthreads();
        int wbase = (w > 0) ? warpsum[w - 1] : 0;
        int incl = x + wbase;
        if (i < NN) g_off[i] = carry + incl - v;
        int tot = warpsum[31];
        __syncthreads();
        if (t == 0) carry += tot;
        __syncthreads();
    }
    if (t == 0) g_off[NN] = carry;
}

__global__ void k_cursor() {
    int i = blockIdx.x * blockDim.x + threadIdx.x;
    if (i < NN) g_cur[i] = g_off[i];
}

__global__ void k_scatter(const void* __restrict__ ei) {
    int e = blockIdx.x * blockDim.x + threadIdx.x;
    if (e >= ET) return;
    int s, d; load_edge(ei, e, s, d);
    int pos = atomicAdd(&g_cur[d], 1);
    g_srcs[pos] = s;
}

// ---------------- GEMM + fused epilogue --------------------------------------
// g_hh[n,128] = half(A[n,128] @ W[128,128]); logits into g_als/g_ald.
#define GEMM_SMEM ((128 * 128 + 128 * 36) * 4)

__global__ void __launch_bounds__(256) k_gemm(const float* __restrict__ A,
                                              const float* __restrict__ W,
                                              const float* __restrict__ asrc,
                                              const float* __restrict__ adst) {
    extern __shared__ float smem[];
    float* Ws = smem;                 // [128][128]
    float* As = smem + 128 * 128;     // [128][36] transposed

    const float* Ap = A ? A : g_act;
    int t = threadIdx.x;
    int n0 = blockIdx.x * 32;

    {
        const float4* W4 = (const float4*)W;
        float4* Ws4 = (float4*)Ws;
#pragma unroll
        for (int i = 0; i < 16; i++) Ws4[t + i * 256] = W4[t + i * 256];
    }
    {
        int r = t >> 3;
        int cb = (t & 7) * 16;
        int row = n0 + r;
        if (row < NN) {
#pragma unroll
            for (int j = 0; j < 16; j++)
                As[(cb + j) * 36 + r] = Ap[row * 128 + cb + j];
        } else {
#pragma unroll
            for (int j = 0; j < 16; j++) As[(cb + j) * 36 + r] = 0.f;
        }
    }
    __syncthreads();

    int tr = t >> 5, tc = t & 31;
    int r0 = tr * 4, c0 = tc * 4;

    float acc[4][4];
#pragma unroll
    for (int i = 0; i < 4; i++)
#pragma unroll
        for (int j = 0; j < 4; j++) acc[i][j] = 0.f;

#pragma unroll 4
    for (int k = 0; k < 128; k++) {
        float4 a = *(const float4*)&As[k * 36 + r0];
        float4 b = *(const float4*)&Ws[k * 128 + c0];
        acc[0][0] += a.x * b.x; acc[0][1] += a.x * b.y; acc[0][2] += a.x * b.z; acc[0][3] += a.x * b.w;
        acc[1][0] += a.y * b.x; acc[1][1] += a.y * b.y; acc[1][2] += a.y * b.z; acc[1][3] += a.y * b.w;
        acc[2][0] += a.z * b.x; acc[2][1] += a.z * b.y; acc[2][2] += a.z * b.z; acc[2][3] += a.z * b.w;
        acc[3][0] += a.w * b.x; acc[3][1] += a.w * b.y; acc[3][2] += a.w * b.z; acc[3][3] += a.w * b.w;
    }

    // epilogue: half store + segmented logit reduction (head0=lanes 0..15)
    float4 s4 = *(const float4*)&asrc[c0];
    float4 d4 = *(const float4*)&adst[c0];
#pragma unroll
    for (int i = 0; i < 4; i++) {
        int row = n0 + r0 + i;
        float ps = acc[i][0] * s4.x + acc[i][1] * s4.y + acc[i][2] * s4.z + acc[i][3] * s4.w;
        float pd = acc[i][0] * d4.x + acc[i][1] * d4.y + acc[i][2] * d4.z + acc[i][3] * d4.w;
#pragma unroll
        for (int off = 8; off; off >>= 1) {
            ps += __shfl_xor_sync(0xffffffffu, ps, off);
            pd += __shfl_xor_sync(0xffffffffu, pd, off);
        }
        if (row < NN) {
            if (tc == 0)  { g_als[row * 2]     = ps; g_ald[row * 2]     = pd; }
            if (tc == 16) { g_als[row * 2 + 1] = ps; g_ald[row * 2 + 1] = pd; }
            union { __half2 h2[2]; uint2 u; } cv;
            cv.h2[0] = __floats2half2_rn(acc[i][0], acc[i][1]);
            cv.h2[1] = __floats2half2_rn(acc[i][2], acc[i][3]);
            *(uint2*)&g_hh[row * 128 + c0] = cv.u;
        }
    }
}

// ---------------- zero BN stats ----------------------------------------------
__global__ void k_zstat() {
    int t = threadIdx.x;
    if (t < FF) { g_sum[t] = 0.f; g_sq[t] = 0.f; }
}

// ---------------- fused aggregation (layers 0/1): warp per dst node ----------
// act = softmax-weighted sum of h[src] + b; BN stats accumulated.
__global__ void __launch_bounds__(256) k_aggr(const float* __restrict__ b) {
    __shared__ float ssum[FF], ssq[FF];
    int t = threadIdx.x, lane = t & 31, w = t >> 5;
    if (t < FF) { ssum[t] = 0.f; ssq[t] = 0.f; }
    __syncthreads();

    int node = blockIdx.x * 8 + w;
    int c = lane * 4;
    float v0 = 0.f, v1 = 0.f, v2 = 0.f, v3 = 0.f;
    if (node < NN) {
        int hd = lane >> 4;
        int beg = g_off[node], end = g_off[node + 1];
        float ald = g_ald[node * 2 + hd];
        float a0 = 0.f, a1 = 0.f, a2 = 0.f, a3 = 0.f, den = 0.f;
        for (int base = beg; base < end; base += 32) {
            int myidx = (base + lane < end) ? g_srcs[base + lane] : 0;
            int cnt = min(32, end - base);
            for (int j = 0; j < cnt; j++) {
                int s = __shfl_sync(0xffffffffu, myidx, j);
                float e = g_als[s * 2 + hd] + ald;
                e = (e > 0.f) ? e : SLOPE * e;
                float wg = __expf(e);
                den += wg;
                uint2 u = *(const uint2*)&g_hh[s * 128 + c];
                float2 f0 = __half22float2(*(__half2*)&u.x);
                float2 f1 = __half22float2(*(__half2*)&u.y);
                a0 += wg * f0.x; a1 += wg * f0.y;
                a2 += wg * f1.x; a3 += wg * f1.y;
            }
        }
        float inv = 1.f / (den + 1e-16f);
        float4 bb = *(const float4*)&b[c];
        v0 = a0 * inv + bb.x;
        v1 = a1 * inv + bb.y;
        v2 = a2 * inv + bb.z;
        v3 = a3 * inv + bb.w;
        *(float4*)&g_act[node * 128 + c] = make_float4(v0, v1, v2, v3);
    }
    atomicAdd(&ssum[c + 0], v0); atomicAdd(&ssq[c + 0], v0 * v0);
    atomicAdd(&ssum[c + 1], v1); atomicAdd(&ssq[c + 1], v1 * v1);
    atomicAdd(&ssum[c + 2], v2); atomicAdd(&ssq[c + 2], v2 * v2);
    atomicAdd(&ssum[c + 3], v3); atomicAdd(&ssq[c + 3], v3 * v3);
    __syncthreads();
    if (t < FF) { atomicAdd(&g_sum[t], ssum[t]); atomicAdd(&g_sq[t], ssq[t]); }
}

// ---------------- fused aggregation (layer 2): head-mean output --------------
__global__ void __launch_bounds__(256) k_aggr_out(const float* __restrict__ b2,
                                                  float* __restrict__ out) {
    int t = threadIdx.x, lane = t & 31, w = t >> 5;
    int node = blockIdx.x * 8 + w;
    if (node >= NN) return;
    int c = lane * 4;
    int hd = lane >> 4;
    int beg = g_off[node], end = g_off[node + 1];
    float ald = g_ald[node * 2 + hd];
    float a0 = 0.f, a1 = 0.f, a2 = 0.f, a3 = 0.f, den = 0.f;
    for (int base = beg; base < end; base += 32) {
        int myidx = (base + lane < end) ? g_srcs[base + lane] : 0;
        int cnt = min(32, end - base);
        for (int j = 0; j < cnt; j++) {
            int s = __shfl_sync(0xffffffffu, myidx, j);
            float e = g_als[s * 2 + hd] + ald;
            e = (e > 0.f) ? e : SLOPE * e;
            float wg = __expf(e);
            den += wg;
            uint2 u = *(const uint2*)&g_hh[s * 128 + c];
            float2 f0 = __half22float2(*(__half2*)&u.x);
            float2 f1 = __half22float2(*(__half2*)&u.y);
            a0 += wg * f0.x; a1 += wg * f0.y;
            a2 += wg * f1.x; a3 += wg * f1.y;
        }
    }
    float inv = 1.f / (den + 1e-16f);
    float r0 = a0 * inv, r1 = a1 * inv, r2 = a2 * inv, r3 = a3 * inv;
    // head mean: lane L and L^16 hold head0/head1 for the same channel pair
    r0 = 0.5f * (r0 + __shfl_xor_sync(0xffffffffu, r0, 16));
    r1 = 0.5f * (r1 + __shfl_xor_sync(0xffffffffu, r1, 16));
    r2 = 0.5f * (r2 + __shfl_xor_sync(0xffffffffu, r2, 16));
    r3 = 0.5f * (r3 + __shfl_xor_sync(0xffffffffu, r3, 16));
    if (lane < 16) {
        float4 bb = *(const float4*)&b2[c];
        *(float4*)&out[node * 64 + c] =
            make_float4(r0 + bb.x, r1 + bb.y, r2 + bb.z, r3 + bb.w);
    }
}

// ---------------- batchnorm + relu (in place on g_act) -----------------------
__global__ void k_bn(const float* __restrict__ g, const float* __restrict__ be) {
    int i = blockIdx.x * blockDim.x + threadIdx.x;     // float4 index
    if (i >= NN * 32) return;
    int c = (i & 31) * 4;
    const float invn = 1.f / (float)NN;
    float4 v  = *(const float4*)&g_act[i * 4];
    float4 s  = *(const float4*)&g_sum[c];
    float4 q  = *(const float4*)&g_sq[c];
    float4 gg = *(const float4*)&g[c];
    float4 bb = *(const float4*)&be[c];

    float mu, var, y;
    mu = s.x * invn; var = q.x * invn - mu * mu;
    y = (v.x - mu) * rsqrtf(var + EPSBN) * gg.x + bb.x; v.x = fmaxf(y, 0.f);
    mu = s.y * invn; var = q.y * invn - mu * mu;
    y = (v.y - mu) * rsqrtf(var + EPSBN) * gg.y + bb.y; v.y = fmaxf(y, 0.f);
    mu = s.z * invn; var = q.z * invn - mu * mu;
    y = (v.z - mu) * rsqrtf(var + EPSBN) * gg.z + bb.z; v.z = fmaxf(y, 0.f);
    mu = s.w * invn; var = q.w * invn - mu * mu;
    y = (v.w - mu) * rsqrtf(var + EPSBN) * gg.w + bb.w; v.w = fmaxf(y, 0.f);

    *(float4*)&g_act[i * 4] = v;
}

// ---------------- launch -----------------------------------------------------
extern "C" void kernel_launch(void* const* d_in, const int* in_sizes, int n_in,
                              void* d_out, int out_size) {
    (void)in_sizes; (void)n_in; (void)out_size;
    const float* x      = (const float*)d_in[0];
    const void*  ei     = d_in[1];
    const float* W0  = (const float*)d_in[2];
    const float* as0 = (const float*)d_in[3];
    const float* ad0 = (const float*)d_in[4];
    const float* b0  = (const float*)d_in[5];
    const float* g0  = (const float*)d_in[6];
    const float* be0 = (const float*)d_in[7];
    const float* W1  = (const float*)d_in[8];
    const float* as1 = (const float*)d_in[9];
    const float* ad1 = (const float*)d_in[10];
    const float* b1  = (const float*)d_in[11];
    const float* g1  = (const float*)d_in[12];
    const float* be1 = (const float*)d_in[13];
    const float* W2  = (const float*)d_in[14];
    const float* as2 = (const float*)d_in[15];
    const float* ad2 = (const float*)d_in[16];
    const float* b2  = (const float*)d_in[17];
    float* out = (float*)d_out;

    cudaFuncSetAttribute(k_gemm, cudaFuncAttributeMaxDynamicSharedMemorySize,
                         GEMM_SMEM);

    const int GB  = (NN + 31) / 32;
    const int NB  = (NN + 255) / 256;
    const int EB  = (ET + 255) / 256;
    const int AB  = (NN + 7) / 8;
    const int BNB = (NN * 32 + 255) / 256;

    // ---- CSR build (once per launch, reused by 3 edge passes) ----
    k_detect<<<1, 32>>>((const int*)ei);
    k_zdeg<<<NB, 256>>>();
    k_hist<<<EB, 256>>>(ei);
    k_scan<<<1, 1024>>>();
    k_cursor<<<NB, 256>>>();
    k_scatter<<<EB, 256>>>(ei);

    // ---- layer 0 ----
    k_gemm<<<GB, 256, GEMM_SMEM>>>(x, W0, as0, ad0);
    k_zstat<<<1, 128>>>();
    k_aggr<<<AB, 256>>>(b0);
    k_bn<<<BNB, 256>>>(g0, be0);

    // ---- layer 1 ----
    k_gemm<<<GB, 256, GEMM_SMEM>>>(nullptr, W1, as1, ad1);
    k_zstat<<<1, 128>>>();
    k_aggr<<<AB, 256>>>(b1);
    k_bn<<<BNB, 256>>>(g1, be1);

    // ---- layer 2 (mean over heads, no BN) ----
    k_gemm<<<GB, 256, GEMM_SMEM>>>(nullptr, W2, as2, ad2);
    k_aggr_out<<<AB, 256>>>(b2, out);
}

// round 4
// speedup vs baseline: 1.7451x; 1.0865x over previous
#include <cuda_runtime.h>
#include <cuda_fp16.h>

#define NN 50000
#define EE 800000
#define ET (EE + NN)
#define FF 128
#define SLOPE 0.2f
#define EPSBN 1e-5f
#define NB1024 ((NN + 1023) / 1024)

// ---------------- scratch (device globals) -----------------------------------
__device__ __align__(16) __half g_hh[NN * FF];   // post-GEMM features (half)
__device__ __align__(16) float g_act[NN * FF];   // layer activations (fp32)
__device__ __align__(16) float g_als[NN * 2];    // src logits per head
__device__ __align__(16) float g_ald[NN * 2];    // dst logits per head
__device__ __align__(16) float g_sum[FF];        // BN channel sums
__device__ __align__(16) float g_sq[FF];         // BN channel sum sq
__device__ int g_deg[NN];                        // in-degree
__device__ int g_off[NN + 1];                    // CSR offsets
__device__ int g_cur[NN];                        // scatter cursors
__device__ int g_srcs[ET];                       // CSR src lists (by dst)
__device__ int g_bsum[64];                       // scan block sums
__device__ int g_boff[64];                       // scan block offsets
__device__ int g_is64;                           // edge dtype flag

// ---------------- detect dtype + zero degree ----------------------------------
__global__ void k_detect(const int* __restrict__ ei32) {
    int i = blockIdx.x * blockDim.x + threadIdx.x;
    if (i < NN) g_deg[i] = 0;
    if (blockIdx.x == 0 && threadIdx.x < 32) {
        int acc = 0;
        for (int k = threadIdx.x; k < 2048; k += 32) acc |= ei32[2 * k + 1];
#pragma unroll
        for (int off = 16; off; off >>= 1)
            acc |= __shfl_xor_sync(0xffffffffu, acc, off);
        if (threadIdx.x == 0) g_is64 = (acc == 0) ? 1 : 0;
    }
}

__device__ __forceinline__ void load_edge(const void* ei, int e, int& s, int& d) {
    if (e < EE) {
        if (g_is64) {
            const long long* e64 = (const long long*)ei;
            s = (int)e64[e]; d = (int)e64[EE + e];
        } else {
            const int* e32 = (const int*)ei;
            s = e32[e]; d = e32[EE + e];
        }
        s = min(max(s, 0), NN - 1);
        d = min(max(d, 0), NN - 1);
    } else {
        s = d = e - EE;
    }
}

__global__ void k_hist(const void* __restrict__ ei) {
    int e = blockIdx.x * blockDim.x + threadIdx.x;
    if (e >= ET) return;
    int s, d; load_edge(ei, e, s, d);
    atomicAdd(&g_deg[d], 1);
}

// ---------------- multi-block scan ---------------------------------------------
__global__ void __launch_bounds__(1024) k_scanA() {
    __shared__ int warpsum[32];
    int t = threadIdx.x, lane = t & 31, w = t >> 5;
    int i = blockIdx.x * 1024 + t;
    int v = (i < NN) ? g_deg[i] : 0;
    int x = v;
#pragma unroll
    for (int off = 1; off < 32; off <<= 1) {
        int y = __shfl_up_sync(0xffffffffu, x, off);
        if (lane >= off) x += y;
    }
    if (lane == 31) warpsum[w] = x;
    __syncthreads();
    if (w == 0) {
        int s = warpsum[lane];
#pragma unroll
        for (int off = 1; off < 32; off <<= 1) {
            int y = __shfl_up_sync(0xffffffffu, s, off);
            if (lane >= off) s += y;
        }
        warpsum[lane] = s;
    }
    __syncthreads();
    int wbase = (w > 0) ? warpsum[w - 1] : 0;
    int incl = x + wbase;
    if (i < NN) g_off[i] = incl - v;      // exclusive, block-local
    if (t == 1023) g_bsum[blockIdx.x] = incl;
}

__global__ void k_scanB() {
    if (threadIdx.x == 0) {
        int run = 0;
        for (int b = 0; b < NB1024; b++) { g_boff[b] = run; run += g_bsum[b]; }
    }
}

__global__ void k_scanC() {
    int i = blockIdx.x * blockDim.x + threadIdx.x;
    if (i < NN) {
        int off = g_off[i] + g_boff[i >> 10];
        g_off[i] = off;
        g_cur[i] = off;
    }
    if (i == 0) g_off[NN] = ET;
}

__global__ void k_scatter(const void* __restrict__ ei) {
    int e = blockIdx.x * blockDim.x + threadIdx.x;
    if (e >= ET) return;
    int s, d; load_edge(ei, e, s, d);
    int pos = atomicAdd(&g_cur[d], 1);
    g_srcs[pos] = s;
}

// ---------------- GEMM + fused epilogue (+ BN stat zeroing) -------------------
#define GEMM_SMEM ((128 * 128 + 128 * 36) * 4)

__global__ void __launch_bounds__(256) k_gemm(const float* __restrict__ A,
                                              const float* __restrict__ W,
                                              const float* __restrict__ asrc,
                                              const float* __restrict__ adst) {
    extern __shared__ float smem[];
    float* Ws = smem;                 // [128][128]
    float* As = smem + 128 * 128;     // [128][36] transposed

    const float* Ap = A ? A : g_act;
    int t = threadIdx.x;
    int n0 = blockIdx.x * 32;

    if (blockIdx.x == 0 && t < FF) { g_sum[t] = 0.f; g_sq[t] = 0.f; }

    {
        const float4* W4 = (const float4*)W;
        float4* Ws4 = (float4*)Ws;
#pragma unroll
        for (int i = 0; i < 16; i++) Ws4[t + i * 256] = W4[t + i * 256];
    }
    {
        int r = t >> 3;
        int cb = (t & 7) * 16;
        int row = n0 + r;
        if (row < NN) {
#pragma unroll
            for (int j = 0; j < 16; j++)
                As[(cb + j) * 36 + r] = Ap[row * 128 + cb + j];
        } else {
#pragma unroll
            for (int j = 0; j < 16; j++) As[(cb + j) * 36 + r] = 0.f;
        }
    }
    __syncthreads();

    int tr = t >> 5, tc = t & 31;
    int r0 = tr * 4, c0 = tc * 4;

    float acc[4][4];
#pragma unroll
    for (int i = 0; i < 4; i++)
#pragma unroll
        for (int j = 0; j < 4; j++) acc[i][j] = 0.f;

#pragma unroll 4
    for (int k = 0; k < 128; k++) {
        float4 a = *(const float4*)&As[k * 36 + r0];
        float4 b = *(const float4*)&Ws[k * 128 + c0];
        acc[0][0] += a.x * b.x; acc[0][1] += a.x * b.y; acc[0][2] += a.x * b.z; acc[0][3] += a.x * b.w;
        acc[1][0] += a.y * b.x; acc[1][1] += a.y * b.y; acc[1][2] += a.y * b.z; acc[1][3] += a.y * b.w;
        acc[2][0] += a.z * b.x; acc[2][1] += a.z * b.y; acc[2][2] += a.z * b.z; acc[2][3] += a.z * b.w;
        acc[3][0] += a.w * b.x; acc[3][1] += a.w * b.y; acc[3][2] += a.w * b.z; acc[3][3] += a.w * b.w;
    }

    float4 s4 = *(const float4*)&asrc[c0];
    float4 d4 = *(const float4*)&adst[c0];
#pragma unroll
    for (int i = 0; i < 4; i++) {
        int row = n0 + r0 + i;
        float ps = acc[i][0] * s4.x + acc[i][1] * s4.y + acc[i][2] * s4.z + acc[i][3] * s4.w;
        float pd = acc[i][0] * d4.x + acc[i][1] * d4.y + acc[i][2] * d4.z + acc[i][3] * d4.w;
#pragma unroll
        for (int off = 8; off; off >>= 1) {
            ps += __shfl_xor_sync(0xffffffffu, ps, off);
            pd += __shfl_xor_sync(0xffffffffu, pd, off);
        }
        if (row < NN) {
            if (tc == 0)  { g_als[row * 2]     = ps; g_ald[row * 2]     = pd; }
            if (tc == 16) { g_als[row * 2 + 1] = ps; g_ald[row * 2 + 1] = pd; }
            union { __half2 h2[2]; uint2 u; } cv;
            cv.h2[0] = __floats2half2_rn(acc[i][0], acc[i][1]);
            cv.h2[1] = __floats2half2_rn(acc[i][2], acc[i][3]);
            *(uint2*)&g_hh[row * 128 + c0] = cv.u;
        }
    }
}

// ---------------- aggregation core (warp per dst node) ------------------------
// Per 32-edge chunk: each lane precomputes exp-weights for BOTH heads of its
// own edge (parallel g_als loads), then broadcast loop does shfl+gather+FMA.
__device__ __forceinline__ void aggr_node(int node, int lane, int hd, int c,
                                          float& a0, float& a1, float& a2,
                                          float& a3, float& den) {
    int beg = g_off[node], end = g_off[node + 1];
    float2 aldv = *(const float2*)&g_ald[node * 2];

    for (int base = beg; base < end; base += 32) {
        int idx = base + lane;
        int s = 0; float w0 = 0.f, w1 = 0.f;
        if (idx < end) {
            s = g_srcs[idx];
            float2 al = *(const float2*)&g_als[s * 2];
            float e0 = al.x + aldv.x; e0 = (e0 > 0.f) ? e0 : SLOPE * e0;
            float e1 = al.y + aldv.y; e1 = (e1 > 0.f) ? e1 : SLOPE * e1;
            w0 = __expf(e0); w1 = __expf(e1);
        }
        int cnt = min(32, end - base);
#pragma unroll 4
        for (int j = 0; j < 32; j++) {
            if (j >= cnt) break;
            int sj = __shfl_sync(0xffffffffu, s, j);
            float u0 = __shfl_sync(0xffffffffu, w0, j);
            float u1 = __shfl_sync(0xffffffffu, w1, j);
            float wg = hd ? u1 : u0;
            uint2 u = *(const uint2*)&g_hh[sj * 128 + c];
            float2 f0 = __half22float2(*(__half2*)&u.x);
            float2 f1 = __half22float2(*(__half2*)&u.y);
            a0 += wg * f0.x; a1 += wg * f0.y;
            a2 += wg * f1.x; a3 += wg * f1.y;
            den += wg;
        }
    }
}

// ---------------- fused aggregation (layers 0/1) + BN stats -------------------
__global__ void __launch_bounds__(256) k_aggr(const float* __restrict__ b) {
    __shared__ float ssum[FF], ssq[FF];
    int t = threadIdx.x, lane = t & 31, w = t >> 5;
    if (t < FF) { ssum[t] = 0.f; ssq[t] = 0.f; }
    __syncthreads();

    int node = blockIdx.x * 8 + w;
    int c = lane * 4;
    float v0 = 0.f, v1 = 0.f, v2 = 0.f, v3 = 0.f;
    if (node < NN) {
        int hd = lane >> 4;
        float a0 = 0.f, a1 = 0.f, a2 = 0.f, a3 = 0.f, den = 0.f;
        aggr_node(node, lane, hd, c, a0, a1, a2, a3, den);
        float inv = 1.f / (den + 1e-16f);
        float4 bb = *(const float4*)&b[c];
        v0 = a0 * inv + bb.x;
        v1 = a1 * inv + bb.y;
        v2 = a2 * inv + bb.z;
        v3 = a3 * inv + bb.w;
        *(float4*)&g_act[node * 128 + c] = make_float4(v0, v1, v2, v3);
    }
    atomicAdd(&ssum[c + 0], v0); atomicAdd(&ssq[c + 0], v0 * v0);
    atomicAdd(&ssum[c + 1], v1); atomicAdd(&ssq[c + 1], v1 * v1);
    atomicAdd(&ssum[c + 2], v2); atomicAdd(&ssq[c + 2], v2 * v2);
    atomicAdd(&ssum[c + 3], v3); atomicAdd(&ssq[c + 3], v3 * v3);
    __syncthreads();
    if (t < FF) { atomicAdd(&g_sum[t], ssum[t]); atomicAdd(&g_sq[t], ssq[t]); }
}

// ---------------- fused aggregation (layer 2): head-mean output ---------------
__global__ void __launch_bounds__(256) k_aggr_out(const float* __restrict__ b2,
                                                  float* __restrict__ out) {
    int t = threadIdx.x, lane = t & 31, w = t >> 5;
    int node = blockIdx.x * 8 + w;
    if (node >= NN) return;
    int c = lane * 4;
    int hd = lane >> 4;
    float a0 = 0.f, a1 = 0.f, a2 = 0.f, a3 = 0.f, den = 0.f;
    aggr_node(node, lane, hd, c, a0, a1, a2, a3, den);
    float inv = 1.f / (den + 1e-16f);
    float r0 = a0 * inv, r1 = a1 * inv, r2 = a2 * inv, r3 = a3 * inv;
    r0 = 0.5f * (r0 + __shfl_xor_sync(0xffffffffu, r0, 16));
    r1 = 0.5f * (r1 + __shfl_xor_sync(0xffffffffu, r1, 16));
    r2 = 0.5f * (r2 + __shfl_xor_sync(0xffffffffu, r2, 16));
    r3 = 0.5f * (r3 + __shfl_xor_sync(0xffffffffu, r3, 16));
    if (lane < 16) {
        float4 bb = *(const float4*)&b2[c];
        *(float4*)&out[node * 64 + c] =
            make_float4(r0 + bb.x, r1 + bb.y, r2 + bb.z, r3 + bb.w);
    }
}

// ---------------- batchnorm + relu (in place on g_act) -----------------------
__global__ void k_bn(const float* __restrict__ g, const float* __restrict__ be) {
    int i = blockIdx.x * blockDim.x + threadIdx.x;
    if (i >= NN * 32) return;
    int c = (i & 31) * 4;
    const float invn = 1.f / (float)NN;
    float4 v  = *(const float4*)&g_act[i * 4];
    float4 s  = *(const float4*)&g_sum[c];
    float4 q  = *(const float4*)&g_sq[c];
    float4 gg = *(const float4*)&g[c];
    float4 bb = *(const float4*)&be[c];

    float mu, var, y;
    mu = s.x * invn; var = q.x * invn - mu * mu;
    y = (v.x - mu) * rsqrtf(var + EPSBN) * gg.x + bb.x; v.x = fmaxf(y, 0.f);
    mu = s.y * invn; var = q.y * invn - mu * mu;
    y = (v.y - mu) * rsqrtf(var + EPSBN) * gg.y + bb.y; v.y = fmaxf(y, 0.f);
    mu = s.z * invn; var = q.z * invn - mu * mu;
    y = (v.z - mu) * rsqrtf(var + EPSBN) * gg.z + bb.z; v.z = fmaxf(y, 0.f);
    mu = s.w * invn; var = q.w * invn - mu * mu;
    y = (v.w - mu) * rsqrtf(var + EPSBN) * gg.w + bb.w; v.w = fmaxf(y, 0.f);

    *(float4*)&g_act[i * 4] = v;
}

// ---------------- launch -----------------------------------------------------
extern "C" void kernel_launch(void* const* d_in, const int* in_sizes, int n_in,
                              void* d_out, int out_size) {
    (void)in_sizes; (void)n_in; (void)out_size;
    const float* x      = (const float*)d_in[0];
    const void*  ei     = d_in[1];
    const float* W0  = (const float*)d_in[2];
    const float* as0 = (const float*)d_in[3];
    const float* ad0 = (const float*)d_in[4];
    const float* b0  = (const float*)d_in[5];
    const float* g0  = (const float*)d_in[6];
    const float* be0 = (const float*)d_in[7];
    const float* W1  = (const float*)d_in[8];
    const float* as1 = (const float*)d_in[9];
    const float* ad1 = (const float*)d_in[10];
    const float* b1  = (const float*)d_in[11];
    const float* g1  = (const float*)d_in[12];
    const float* be1 = (const float*)d_in[13];
    const float* W2  = (const float*)d_in[14];
    const float* as2 = (const float*)d_in[15];
    const float* ad2 = (const float*)d_in[16];
    const float* b2  = (const float*)d_in[17];
    float* out = (float*)d_out;

    cudaFuncSetAttribute(k_gemm, cudaFuncAttributeMaxDynamicSharedMemorySize,
                         GEMM_SMEM);

    const int GB  = (NN + 31) / 32;
    const int NB  = (NN + 255) / 256;
    const int EB  = (ET + 255) / 256;
    const int AB  = (NN + 7) / 8;
    const int BNB = (NN * 32 + 255) / 256;

    // ---- CSR build ----
    k_detect<<<NB, 256>>>((const int*)ei);
    k_hist<<<EB, 256>>>(ei);
    k_scanA<<<NB1024, 1024>>>();
    k_scanB<<<1, 32>>>();
    k_scanC<<<NB, 256>>>();
    k_scatter<<<EB, 256>>>(ei);

    // ---- layer 0 ----
    k_gemm<<<GB, 256, GEMM_SMEM>>>(x, W0, as0, ad0);
    k_aggr<<<AB, 256>>>(b0);
    k_bn<<<BNB, 256>>>(g0, be0);

    // ---- layer 1 ----
    k_gemm<<<GB, 256, GEMM_SMEM>>>(nullptr, W1, as1, ad1);
    k_aggr<<<AB, 256>>>(b1);
    k_bn<<<BNB, 256>>>(g1, be1);

    // ---- layer 2 ----
    k_gemm<<<GB, 256, GEMM_SMEM>>>(nullptr, W2, as2, ad2);
    k_aggr_out<<<AB, 256>>>(b2, out);
}

// round 6
// speedup vs baseline: 2.4956x; 1.4301x over previous
#include <cuda_runtime.h>
#include <cuda_fp16.h>

#define NN 50000
#define EE 800000
#define ET (EE + NN)
#define FF 128
#define SLOPE 0.2f
#define EPSBN 1e-5f
#define NB1024 ((NN + 1023) / 1024)

// ---------------- scratch (device globals) -----------------------------------
__device__ __align__(16) __half g_hh[NN * FF];   // post-GEMM features (half)
__device__ __align__(16) float g_act[NN * FF];   // layer activations (fp32, pre-BN)
__device__ __align__(16) float g_als[NN * 2];    // src logits per head
__device__ __align__(16) float g_ald[NN * 2];    // dst logits per head
__device__ __align__(16) float g_sumA[2][FF];    // BN channel sums (per layer)
__device__ __align__(16) float g_sqA[2][FF];     // BN channel sum sq
__device__ int g_deg[NN];
__device__ int g_off[NN + 1];
__device__ int g_cur[NN];
__device__ int g_srcs[ET];
__device__ int g_bsum[64];
__device__ int g_is64;

// ---------------- detect dtype + zero degree + zero BN stats ------------------
__global__ void k_detect(const int* __restrict__ ei32) {
    int i = blockIdx.x * blockDim.x + threadIdx.x;
    if (i < NN) g_deg[i] = 0;
    if (blockIdx.x == 0) {
        if (threadIdx.x < FF) {
            g_sumA[0][threadIdx.x] = 0.f; g_sqA[0][threadIdx.x] = 0.f;
            g_sumA[1][threadIdx.x] = 0.f; g_sqA[1][threadIdx.x] = 0.f;
        }
        if (threadIdx.x < 32) {
            int acc = 0;
            for (int k = threadIdx.x; k < 2048; k += 32) acc |= ei32[2 * k + 1];
#pragma unroll
            for (int off = 16; off; off >>= 1)
                acc |= __shfl_xor_sync(0xffffffffu, acc, off);
            if (threadIdx.x == 0) g_is64 = (acc == 0) ? 1 : 0;
        }
    }
}

__device__ __forceinline__ void load_edge(const void* ei, int e, int& s, int& d) {
    if (e < EE) {
        if (g_is64) {
            const long long* e64 = (const long long*)ei;
            s = (int)e64[e]; d = (int)e64[EE + e];
        } else {
            const int* e32 = (const int*)ei;
            s = e32[e]; d = e32[EE + e];
        }
        s = min(max(s, 0), NN - 1);
        d = min(max(d, 0), NN - 1);
    } else {
        s = d = e - EE;
    }
}

__global__ void k_hist(const void* __restrict__ ei) {
    int e = blockIdx.x * blockDim.x + threadIdx.x;
    if (e >= ET) return;
    int s, d; load_edge(ei, e, s, d);
    atomicAdd(&g_deg[d], 1);
}

// ---------------- multi-block scan ---------------------------------------------
__global__ void __launch_bounds__(1024) k_scanA() {
    __shared__ int warpsum[32];
    int t = threadIdx.x, lane = t & 31, w = t >> 5;
    int i = blockIdx.x * 1024 + t;
    int v = (i < NN) ? g_deg[i] : 0;
    int x = v;
#pragma unroll
    for (int off = 1; off < 32; off <<= 1) {
        int y = __shfl_up_sync(0xffffffffu, x, off);
        if (lane >= off) x += y;
    }
    if (lane == 31) warpsum[w] = x;
    __syncthreads();
    if (w == 0) {
        int s = warpsum[lane];
#pragma unroll
        for (int off = 1; off < 32; off <<= 1) {
            int y = __shfl_up_sync(0xffffffffu, s, off);
            if (lane >= off) s += y;
        }
        warpsum[lane] = s;
    }
    __syncthreads();
    int wbase = (w > 0) ? warpsum[w - 1] : 0;
    int incl = x + wbase;
    if (i < NN) g_off[i] = incl - v;      // exclusive, block-local
    if (t == 1023) g_bsum[blockIdx.x] = incl;
}

// scanC: adds block offsets (computed redundantly per block) + init cursors
__global__ void k_scanC() {
    __shared__ int soff[64];
    int t = threadIdx.x;
    if (t < 64) {
        int v = (t < NB1024) ? g_bsum[t] : 0;
        int lane = t & 31;
        int x = v;
#pragma unroll
        for (int off = 1; off < 32; off <<= 1) {
            int y = __shfl_up_sync(0xffffffffu, x, off);
            if (lane >= off) x += y;
        }
        soff[t] = x - v;                  // exclusive within warp
    }
    __syncthreads();
    // add warp0 total to warp1's entries
    if (t >= 32 && t < 64) {
        int w0tot = soff[31] + ((31 < NB1024) ? g_bsum[31] : 0);
        soff[t] += w0tot;
    }
    __syncthreads();
    int i = blockIdx.x * blockDim.x + t;
    if (i < NN) {
        int off = g_off[i] + soff[i >> 10];
        g_off[i] = off;
        g_cur[i] = off;
    }
    if (i == 0) g_off[NN] = ET;
}

__global__ void k_scatter(const void* __restrict__ ei) {
    int e = blockIdx.x * blockDim.x + threadIdx.x;
    if (e >= ET) return;
    int s, d; load_edge(ei, e, s, d);
    int pos = atomicAdd(&g_cur[d], 1);
    g_srcs[pos] = s;
}

// ---------------- tf32 tensor-core GEMM + fused BN on load + epilogue ---------
#define WS_STRIDE 136
#define AS_STRIDE 132
#define GEMM_SMEM ((128 * WS_STRIDE + 32 * AS_STRIDE) * 4 + 8 * 16 * 2 * 4)

__device__ __forceinline__ unsigned f2tf(float x) {
    unsigned u;
    asm("cvt.rna.tf32.f32 %0, %1;" : "=r"(u) : "f"(x));
    return u;
}

__device__ __forceinline__ void mma_tf32(float& d0, float& d1, float& d2, float& d3,
                                         unsigned a0, unsigned a1, unsigned a2,
                                         unsigned a3, unsigned b0, unsigned b1) {
    asm("mma.sync.aligned.m16n8k8.row.col.f32.tf32.tf32.f32 "
        "{%0,%1,%2,%3},{%4,%5,%6,%7},{%8,%9},{%0,%1,%2,%3};"
        : "+f"(d0), "+f"(d1), "+f"(d2), "+f"(d3)
        : "r"(a0), "r"(a1), "r"(a2), "r"(a3), "r"(b0), "r"(b1));
}

__global__ void __launch_bounds__(256) k_gemm(const float* __restrict__ A,
                                              const float* __restrict__ W,
                                              const float* __restrict__ asrc,
                                              const float* __restrict__ adst,
                                              const float* __restrict__ bng,
                                              const float* __restrict__ bnb,
                                              int bnbuf) {
    extern __shared__ unsigned smem[];
    unsigned* Ws = smem;                          // [128][136]
    unsigned* As = smem + 128 * WS_STRIDE;        // [32][132]
    float* sps = (float*)(As + 32 * AS_STRIDE);   // [8][16]
    float* spd = sps + 8 * 16;                    // [8][16]

    const float* Ap = A ? A : g_act;
    int t = threadIdx.x;
    int n0 = blockIdx.x * 32;

    // ---- load W tile (all of W) as tf32, row-major stride 136 ----
    {
        int c4 = (t & 31) * 4;
#pragma unroll
        for (int i = 0; i < 16; i++) {
            int k = (t >> 5) + i * 8;
            float4 w4 = *(const float4*)&W[k * 128 + c4];
            unsigned* dst = &Ws[k * WS_STRIDE + c4];
            dst[0] = f2tf(w4.x); dst[1] = f2tf(w4.y);
            dst[2] = f2tf(w4.z); dst[3] = f2tf(w4.w);
        }
    }
    // ---- load A tile (32 rows) with optional fused BN+ReLU ----
    {
        int c4 = (t & 31) * 4;
        float4 sc = make_float4(1.f, 1.f, 1.f, 1.f);
        float4 sh = make_float4(0.f, 0.f, 0.f, 0.f);
        bool bn = (bnbuf >= 0);
        if (bn) {
            const float invn = 1.f / (float)NN;
            float4 s = *(const float4*)&g_sumA[bnbuf][c4];
            float4 q = *(const float4*)&g_sqA[bnbuf][c4];
            float4 gg = *(const float4*)&bng[c4];
            float4 bb = *(const float4*)&bnb[c4];
            float mu, var, r;
            mu = s.x * invn; var = q.x * invn - mu * mu; r = rsqrtf(var + EPSBN) * gg.x;
            sc.x = r; sh.x = bb.x - mu * r;
            mu = s.y * invn; var = q.y * invn - mu * mu; r = rsqrtf(var + EPSBN) * gg.y;
            sc.y = r; sh.y = bb.y - mu * r;
            mu = s.z * invn; var = q.z * invn - mu * mu; r = rsqrtf(var + EPSBN) * gg.z;
            sc.z = r; sh.z = bb.z - mu * r;
            mu = s.w * invn; var = q.w * invn - mu * mu; r = rsqrtf(var + EPSBN) * gg.w;
            sc.w = r; sh.w = bb.w - mu * r;
        }
#pragma unroll
        for (int i = 0; i < 4; i++) {
            int r = (t >> 5) + i * 8;       // 0..31
            int row = n0 + r;
            float4 v = make_float4(0.f, 0.f, 0.f, 0.f);
            if (row < NN) v = *(const float4*)&Ap[row * 128 + c4];
            if (bn) {
                v.x = fmaxf(v.x * sc.x + sh.x, 0.f);
                v.y = fmaxf(v.y * sc.y + sh.y, 0.f);
                v.z = fmaxf(v.z * sc.z + sh.z, 0.f);
                v.w = fmaxf(v.w * sc.w + sh.w, 0.f);
            }
            unsigned* dst = &As[r * AS_STRIDE + c4];
            dst[0] = f2tf(v.x); dst[1] = f2tf(v.y);
            dst[2] = f2tf(v.z); dst[3] = f2tf(v.w);
        }
    }
    __syncthreads();

    int lane = t & 31, wid = t >> 5;
    int g = lane >> 2, tg = lane & 3;
    int mg = wid & 1, ng = wid >> 1;

    float acc[4][4];
#pragma unroll
    for (int j = 0; j < 4; j++)
#pragma unroll
        for (int e = 0; e < 4; e++) acc[j][e] = 0.f;

    const unsigned* Ab = &As[(mg * 16) * AS_STRIDE];
    int rA0 = g * AS_STRIDE, rA1 = (g + 8) * AS_STRIDE;

#pragma unroll
    for (int kk = 0; kk < 16; kk++) {
        int kb = kk * 8;
        unsigned a0 = Ab[rA0 + kb + tg];
        unsigned a1 = Ab[rA1 + kb + tg];
        unsigned a2 = Ab[rA0 + kb + tg + 4];
        unsigned a3 = Ab[rA1 + kb + tg + 4];
#pragma unroll
        for (int j = 0; j < 4; j++) {
            int cb = ng * 32 + j * 8 + g;
            unsigned b0 = Ws[(kb + tg) * WS_STRIDE + cb];
            unsigned b1 = Ws[(kb + tg + 4) * WS_STRIDE + cb];
            mma_tf32(acc[j][0], acc[j][1], acc[j][2], acc[j][3],
                     a0, a1, a2, a3, b0, b1);
        }
    }

    // ---- epilogue: half store + logit partials ----
    int lr0 = mg * 16 + g, lr1 = lr0 + 8;
    int grow0 = n0 + lr0, grow1 = n0 + lr1;
    float ps0 = 0.f, pd0 = 0.f, ps1 = 0.f, pd1 = 0.f;
#pragma unroll
    for (int j = 0; j < 4; j++) {
        int cj = ng * 32 + j * 8 + 2 * tg;
        float asx = asrc[cj], asy = asrc[cj + 1];
        float adx = adst[cj], ady = adst[cj + 1];
        ps0 += acc[j][0] * asx + acc[j][1] * asy;
        pd0 += acc[j][0] * adx + acc[j][1] * ady;
        ps1 += acc[j][2] * asx + acc[j][3] * asy;
        pd1 += acc[j][2] * adx + acc[j][3] * ady;
        if (grow0 < NN)
            *(__half2*)&g_hh[grow0 * 128 + cj] = __floats2half2_rn(acc[j][0], acc[j][1]);
        if (grow1 < NN)
            *(__half2*)&g_hh[grow1 * 128 + cj] = __floats2half2_rn(acc[j][2], acc[j][3]);
    }
#pragma unroll
    for (int off = 1; off <= 2; off <<= 1) {
        ps0 += __shfl_xor_sync(0xffffffffu, ps0, off);
        pd0 += __shfl_xor_sync(0xffffffffu, pd0, off);
        ps1 += __shfl_xor_sync(0xffffffffu, ps1, off);
        pd1 += __shfl_xor_sync(0xffffffffu, pd1, off);
    }
    if (tg == 0) {
        sps[wid * 16 + g] = ps0;     spd[wid * 16 + g] = pd0;
        sps[wid * 16 + g + 8] = ps1; spd[wid * 16 + g + 8] = pd1;
    }
    __syncthreads();
    if (t < 64) {
        int h = t >> 5, lr = t & 31;
        int mg2 = lr >> 4, g16 = lr & 15;
        int wA = 4 * h + mg2, wB = 4 * h + 2 + mg2;
        float ps = sps[wA * 16 + g16] + sps[wB * 16 + g16];
        float pd = spd[wA * 16 + g16] + spd[wB * 16 + g16];
        int row = n0 + lr;
        if (row < NN) { g_als[row * 2 + h] = ps; g_ald[row * 2 + h] = pd; }
    }
}

// ---------------- aggregation core (warp per dst node) ------------------------
__device__ __forceinline__ void aggr_node(int node, int lane, int hd, int c,
                                          float& a0, float& a1, float& a2,
                                          float& a3, float& den) {
    int beg = g_off[node], end = g_off[node + 1];
    float2 aldv = *(const float2*)&g_ald[node * 2];

    for (int base = beg; base < end; base += 32) {
        int idx = base + lane;
        int s = 0; float w0 = 0.f, w1 = 0.f;
        if (idx < end) {
            s = g_srcs[idx];
            float2 al = *(const float2*)&g_als[s * 2];
            float e0 = al.x + aldv.x; e0 = (e0 > 0.f) ? e0 : SLOPE * e0;
            float e1 = al.y + aldv.y; e1 = (e1 > 0.f) ? e1 : SLOPE * e1;
            w0 = __expf(e0); w1 = __expf(e1);
        }
        int cnt = min(32, end - base);
#pragma unroll 4
        for (int j = 0; j < 32; j++) {
            if (j >= cnt) break;
            int sj = __shfl_sync(0xffffffffu, s, j);
            float u0 = __shfl_sync(0xffffffffu, w0, j);
            float u1 = __shfl_sync(0xffffffffu, w1, j);
            float wg = hd ? u1 : u0;
            uint2 u = *(const uint2*)&g_hh[sj * 128 + c];
            float2 f0 = __half22float2(*(__half2*)&u.x);
            float2 f1 = __half22float2(*(__half2*)&u.y);
            a0 += wg * f0.x; a1 += wg * f0.y;
            a2 += wg * f1.x; a3 += wg * f1.y;
            den += wg;
        }
    }
}

// ---------------- fused aggregation (layers 0/1) + BN stats -------------------
__global__ void __launch_bounds__(256) k_aggr(const float* __restrict__ b,
                                              int statbuf) {
    __shared__ float ssum[FF], ssq[FF];
    int t = threadIdx.x, lane = t & 31, w = t >> 5;
    if (t < FF) { ssum[t] = 0.f; ssq[t] = 0.f; }
    __syncthreads();

    int node = blockIdx.x * 8 + w;
    int c = lane * 4;
    float v0 = 0.f, v1 = 0.f, v2 = 0.f, v3 = 0.f;
    if (node < NN) {
        int hd = lane >> 4;
        float a0 = 0.f, a1 = 0.f, a2 = 0.f, a3 = 0.f, den = 0.f;
        aggr_node(node, lane, hd, c, a0, a1, a2, a3, den);
        float inv = 1.f / (den + 1e-16f);
        float4 bb = *(const float4*)&b[c];
        v0 = a0 * inv + bb.x;
        v1 = a1 * inv + bb.y;
        v2 = a2 * inv + bb.z;
        v3 = a3 * inv + bb.w;
        *(float4*)&g_act[node * 128 + c] = make_float4(v0, v1, v2, v3);
    }
    atomicAdd(&ssum[c + 0], v0); atomicAdd(&ssq[c + 0], v0 * v0);
    atomicAdd(&ssum[c + 1], v1); atomicAdd(&ssq[c + 1], v1 * v1);
    atomicAdd(&ssum[c + 2], v2); atomicAdd(&ssq[c + 2], v2 * v2);
    atomicAdd(&ssum[c + 3], v3); atomicAdd(&ssq[c + 3], v3 * v3);
    __syncthreads();
    if (t < FF) {
        atomicAdd(&g_sumA[statbuf][t], ssum[t]);
        atomicAdd(&g_sqA[statbuf][t], ssq[t]);
    }
}

// ---------------- fused aggregation (layer 2): head-mean output ---------------
__global__ void __launch_bounds__(256) k_aggr_out(const float* __restrict__ b2,
                                                  float* __restrict__ out) {
    int t = threadIdx.x, lane = t & 31, w = t >> 5;
    int node = blockIdx.x * 8 + w;
    if (node >= NN) return;
    int c = lane * 4;
    int hd = lane >> 4;
    float a0 = 0.f, a1 = 0.f, a2 = 0.f, a3 = 0.f, den = 0.f;
    aggr_node(node, lane, hd, c, a0, a1, a2, a3, den);
    float inv = 1.f / (den + 1e-16f);
    float r0 = a0 * inv, r1 = a1 * inv, r2 = a2 * inv, r3 = a3 * inv;
    r0 = 0.5f * (r0 + __shfl_xor_sync(0xffffffffu, r0, 16));
    r1 = 0.5f * (r1 + __shfl_xor_sync(0xffffffffu, r1, 16));
    r2 = 0.5f * (r2 + __shfl_xor_sync(0xffffffffu, r2, 16));
    r3 = 0.5f * (r3 + __shfl_xor_sync(0xffffffffu, r3, 16));
    if (lane < 16) {
        float4 bb = *(const float4*)&b2[c];
        *(float4*)&out[node * 64 + c] =
            make_float4(r0 + bb.x, r1 + bb.y, r2 + bb.z, r3 + bb.w);
    }
}

// ---------------- launch -----------------------------------------------------
extern "C" void kernel_launch(void* const* d_in, const int* in_sizes, int n_in,
                              void* d_out, int out_size) {
    (void)in_sizes; (void)n_in; (void)out_size;
    const float* x      = (const float*)d_in[0];
    const void*  ei     = d_in[1];
    const float* W0  = (const float*)d_in[2];
    const float* as0 = (const float*)d_in[3];
    const float* ad0 = (const float*)d_in[4];
    const float* b0  = (const float*)d_in[5];
    const float* g0  = (const float*)d_in[6];
    const float* be0 = (const float*)d_in[7];
    const float* W1  = (const float*)d_in[8];
    const float* as1 = (const float*)d_in[9];
    const float* ad1 = (const float*)d_in[10];
    const float* b1  = (const float*)d_in[11];
    const float* g1  = (const float*)d_in[12];
    const float* be1 = (const float*)d_in[13];
    const float* W2  = (const float*)d_in[14];
    const float* as2 = (const float*)d_in[15];
    const float* ad2 = (const float*)d_in[16];
    const float* b2  = (const float*)d_in[17];
    float* out = (float*)d_out;

    cudaFuncSetAttribute(k_gemm, cudaFuncAttributeMaxDynamicSharedMemorySize,
                         GEMM_SMEM);

    const int GB  = (NN + 31) / 32;
    const int NB  = (NN + 255) / 256;
    const int EB  = (ET + 255) / 256;
    const int AB  = (NN + 7) / 8;

    // ---- CSR build ----
    k_detect<<<NB, 256>>>((const int*)ei);
    k_hist<<<EB, 256>>>(ei);
    k_scanA<<<NB1024, 1024>>>();
    k_scanC<<<NB, 256>>>();
    k_scatter<<<EB, 256>>>(ei);

    // ---- layer 0 ----
    k_gemm<<<GB, 256, GEMM_SMEM>>>(x, W0, as0, ad0, nullptr, nullptr, -1);
    k_aggr<<<AB, 256>>>(b0, 0);

    // ---- layer 1 (BN0 fused into A-load) ----
    k_gemm<<<GB, 256, GEMM_SMEM>>>(nullptr, W1, as1, ad1, g0, be0, 0);
    k_aggr<<<AB, 256>>>(b1, 1);

    // ---- layer 2 (BN1 fused into A-load, head-mean out) ----
    k_gemm<<<GB, 256, GEMM_SMEM>>>(nullptr, W2, as2, ad2, g1, be1, 1);
    k_aggr_out<<<AB, 256>>>(b2, out);
}

// round 7
// speedup vs baseline: 2.9063x; 1.1646x over previous
#include <cuda_runtime.h>
#include <cuda_fp16.h>

#define NN 50000
#define EE 800000
#define ET (EE + NN)
#define FF 128
#define SLOPE 0.2f
#define EPSBN 1e-5f
#define NB1024 ((NN + 1023) / 1024)

// ---------------- scratch (device globals) -----------------------------------
__device__ __align__(16) __half g_hh[NN * FF];   // post-GEMM features (half)
__device__ __align__(16) float g_act[NN * FF];   // layer activations (fp32, pre-BN)
__device__ __align__(16) float g_als[NN * 2];    // src logits per head
__device__ __align__(16) float g_ald[NN * 2];    // dst logits per head
__device__ __align__(16) float g_sumA[2][FF];    // BN channel sums (per layer)
__device__ __align__(16) float g_sqA[2][FF];     // BN channel sum sq
__device__ int g_deg[NN];
__device__ int g_off[NN + 1];
__device__ int g_cur[NN];
__device__ int g_srcs[ET];
__device__ int g_bsum[64];
__device__ int g_is64;

// ---------------- detect dtype + zero degree + zero BN stats ------------------
__global__ void k_detect(const int* __restrict__ ei32) {
    int i = blockIdx.x * blockDim.x + threadIdx.x;
    if (i < NN) g_deg[i] = 0;
    if (blockIdx.x == 0) {
        if (threadIdx.x < FF) {
            g_sumA[0][threadIdx.x] = 0.f; g_sqA[0][threadIdx.x] = 0.f;
            g_sumA[1][threadIdx.x] = 0.f; g_sqA[1][threadIdx.x] = 0.f;
        }
        if (threadIdx.x < 32) {
            int acc = 0;
            for (int k = threadIdx.x; k < 2048; k += 32) acc |= ei32[2 * k + 1];
#pragma unroll
            for (int off = 16; off; off >>= 1)
                acc |= __shfl_xor_sync(0xffffffffu, acc, off);
            if (threadIdx.x == 0) g_is64 = (acc == 0) ? 1 : 0;
        }
    }
}

__device__ __forceinline__ void load_edge(const void* ei, int e, int& s, int& d) {
    if (e < EE) {
        if (g_is64) {
            const long long* e64 = (const long long*)ei;
            s = (int)e64[e]; d = (int)e64[EE + e];
        } else {
            const int* e32 = (const int*)ei;
            s = e32[e]; d = e32[EE + e];
        }
        s = min(max(s, 0), NN - 1);
        d = min(max(d, 0), NN - 1);
    } else {
        s = d = e - EE;
    }
}

__global__ void k_hist(const void* __restrict__ ei) {
    int e = blockIdx.x * blockDim.x + threadIdx.x;
    if (e >= ET) return;
    int s, d; load_edge(ei, e, s, d);
    atomicAdd(&g_deg[d], 1);
}

// ---------------- multi-block scan ---------------------------------------------
__global__ void __launch_bounds__(1024) k_scanA() {
    __shared__ int warpsum[32];
    int t = threadIdx.x, lane = t & 31, w = t >> 5;
    int i = blockIdx.x * 1024 + t;
    int v = (i < NN) ? g_deg[i] : 0;
    int x = v;
#pragma unroll
    for (int off = 1; off < 32; off <<= 1) {
        int y = __shfl_up_sync(0xffffffffu, x, off);
        if (lane >= off) x += y;
    }
    if (lane == 31) warpsum[w] = x;
    __syncthreads();
    if (w == 0) {
        int s = warpsum[lane];
#pragma unroll
        for (int off = 1; off < 32; off <<= 1) {
            int y = __shfl_up_sync(0xffffffffu, s, off);
            if (lane >= off) s += y;
        }
        warpsum[lane] = s;
    }
    __syncthreads();
    int wbase = (w > 0) ? warpsum[w - 1] : 0;
    int incl = x + wbase;
    if (i < NN) g_off[i] = incl - v;      // exclusive, block-local
    if (t == 1023) g_bsum[blockIdx.x] = incl;
}

// scanC: adds block offsets (computed redundantly per block) + init cursors
__global__ void k_scanC() {
    __shared__ int soff[64];
    int t = threadIdx.x;
    if (t < 64) {
        int v = (t < NB1024) ? g_bsum[t] : 0;
        int lane = t & 31;
        int x = v;
#pragma unroll
        for (int off = 1; off < 32; off <<= 1) {
            int y = __shfl_up_sync(0xffffffffu, x, off);
            if (lane >= off) x += y;
        }
        soff[t] = x - v;                  // exclusive within warp
    }
    __syncthreads();
    if (t >= 32 && t < 64) {
        int w0tot = soff[31] + ((31 < NB1024) ? g_bsum[31] : 0);
        soff[t] += w0tot;
    }
    __syncthreads();
    int i = blockIdx.x * blockDim.x + t;
    if (i < NN) {
        int off = g_off[i] + soff[i >> 10];
        g_off[i] = off;
        g_cur[i] = off;
    }
    if (i == 0) g_off[NN] = ET;
}

__global__ void k_scatter(const void* __restrict__ ei) {
    int e = blockIdx.x * blockDim.x + threadIdx.x;
    if (e >= ET) return;
    int s, d; load_edge(ei, e, s, d);
    int pos = atomicAdd(&g_cur[d], 1);
    g_srcs[pos] = s;
}

// ---------------- tf32 tensor-core GEMM, M-tile 128 ---------------------------
// Block: 256 threads (8 warps), tile M=128 x N=128, K=128.
// Warp: mg=wid&3 -> 32 rows (4 row-frags), ng=wid>>2 -> 64 cols (8 n-frags).
// ng*64 aligns with head boundary -> warp-local complete logit partials.
#define WS_STRIDE 136
#define AS_STRIDE 132
#define GEMM_SMEM ((128 * WS_STRIDE + 128 * AS_STRIDE) * 4)

__device__ __forceinline__ unsigned f2tf(float x) {
    unsigned u;
    asm("cvt.rna.tf32.f32 %0, %1;" : "=r"(u) : "f"(x));
    return u;
}

__device__ __forceinline__ void mma_tf32(float* d,
                                         unsigned a0, unsigned a1, unsigned a2,
                                         unsigned a3, unsigned b0, unsigned b1) {
    asm("mma.sync.aligned.m16n8k8.row.col.f32.tf32.tf32.f32 "
        "{%0,%1,%2,%3},{%4,%5,%6,%7},{%8,%9},{%0,%1,%2,%3};"
        : "+f"(d[0]), "+f"(d[1]), "+f"(d[2]), "+f"(d[3])
        : "r"(a0), "r"(a1), "r"(a2), "r"(a3), "r"(b0), "r"(b1));
}

__global__ void __launch_bounds__(256) k_gemm(const float* __restrict__ A,
                                              const float* __restrict__ W,
                                              const float* __restrict__ asrc,
                                              const float* __restrict__ adst,
                                              const float* __restrict__ bng,
                                              const float* __restrict__ bnb,
                                              int bnbuf) {
    extern __shared__ unsigned smem[];
    unsigned* Ws = smem;                          // [128][136]
    unsigned* As = smem + 128 * WS_STRIDE;        // [128][132]

    const float* Ap = A ? A : g_act;
    int t = threadIdx.x;
    int n0 = blockIdx.x * 128;

    // ---- load W (full 128x128) as tf32 ----
    {
        int c4 = (t & 31) * 4;
#pragma unroll
        for (int i = 0; i < 16; i++) {
            int k = (t >> 5) + i * 8;
            float4 w4 = *(const float4*)&W[k * 128 + c4];
            unsigned* dst = &Ws[k * WS_STRIDE + c4];
            dst[0] = f2tf(w4.x); dst[1] = f2tf(w4.y);
            dst[2] = f2tf(w4.z); dst[3] = f2tf(w4.w);
        }
    }
    // ---- load A tile (128 rows) with optional fused BN+ReLU ----
    {
        int c4 = (t & 31) * 4;
        float4 sc = make_float4(1.f, 1.f, 1.f, 1.f);
        float4 sh = make_float4(0.f, 0.f, 0.f, 0.f);
        bool bn = (bnbuf >= 0);
        if (bn) {
            const float invn = 1.f / (float)NN;
            float4 s = *(const float4*)&g_sumA[bnbuf][c4];
            float4 q = *(const float4*)&g_sqA[bnbuf][c4];
            float4 gg = *(const float4*)&bng[c4];
            float4 bb = *(const float4*)&bnb[c4];
            float mu, var, r;
            mu = s.x * invn; var = q.x * invn - mu * mu; r = rsqrtf(var + EPSBN) * gg.x;
            sc.x = r; sh.x = bb.x - mu * r;
            mu = s.y * invn; var = q.y * invn - mu * mu; r = rsqrtf(var + EPSBN) * gg.y;
            sc.y = r; sh.y = bb.y - mu * r;
            mu = s.z * invn; var = q.z * invn - mu * mu; r = rsqrtf(var + EPSBN) * gg.z;
            sc.z = r; sh.z = bb.z - mu * r;
            mu = s.w * invn; var = q.w * invn - mu * mu; r = rsqrtf(var + EPSBN) * gg.w;
            sc.w = r; sh.w = bb.w - mu * r;
        }
#pragma unroll
        for (int i = 0; i < 16; i++) {
            int r = (t >> 5) + i * 8;       // 0..127
            int row = n0 + r;
            float4 v = make_float4(0.f, 0.f, 0.f, 0.f);
            if (row < NN) v = *(const float4*)&Ap[row * 128 + c4];
            if (bn) {
                v.x = fmaxf(v.x * sc.x + sh.x, 0.f);
                v.y = fmaxf(v.y * sc.y + sh.y, 0.f);
                v.z = fmaxf(v.z * sc.z + sh.z, 0.f);
                v.w = fmaxf(v.w * sc.w + sh.w, 0.f);
            }
            unsigned* dst = &As[r * AS_STRIDE + c4];
            dst[0] = f2tf(v.x); dst[1] = f2tf(v.y);
            dst[2] = f2tf(v.z); dst[3] = f2tf(v.w);
        }
    }
    __syncthreads();

    int lane = t & 31, wid = t >> 5;
    int g = lane >> 2, tg = lane & 3;
    int mg = wid & 3, ng = wid >> 2;

    float accA[8][4], accB[8][4];
#pragma unroll
    for (int j = 0; j < 8; j++)
#pragma unroll
        for (int e = 0; e < 4; e++) { accA[j][e] = 0.f; accB[j][e] = 0.f; }

    const int rowA0 = (mg * 32 + g) * AS_STRIDE;
    const int rowA1 = rowA0 + 8 * AS_STRIDE;
    const int rowB0 = rowA0 + 16 * AS_STRIDE;
    const int rowB1 = rowA0 + 24 * AS_STRIDE;

#pragma unroll
    for (int kk = 0; kk < 16; kk++) {
        int kb = kk * 8;
        unsigned aA0 = As[rowA0 + kb + tg];
        unsigned aA1 = As[rowA1 + kb + tg];
        unsigned aA2 = As[rowA0 + kb + tg + 4];
        unsigned aA3 = As[rowA1 + kb + tg + 4];
        unsigned aB0 = As[rowB0 + kb + tg];
        unsigned aB1 = As[rowB1 + kb + tg];
        unsigned aB2 = As[rowB0 + kb + tg + 4];
        unsigned aB3 = As[rowB1 + kb + tg + 4];
#pragma unroll
        for (int j = 0; j < 8; j++) {
            int cb = ng * 64 + j * 8 + g;
            unsigned b0 = Ws[(kb + tg) * WS_STRIDE + cb];
            unsigned b1 = Ws[(kb + tg + 4) * WS_STRIDE + cb];
            mma_tf32(accA[j], aA0, aA1, aA2, aA3, b0, b1);
            mma_tf32(accB[j], aB0, aB1, aB2, aB3, b0, b1);
        }
    }

    // ---- epilogue: half store + complete per-head logit (ng == head) ----
    int r0 = mg * 32 + g;
    float ps0 = 0.f, ps1 = 0.f, ps2 = 0.f, ps3 = 0.f;
    float pd0 = 0.f, pd1 = 0.f, pd2 = 0.f, pd3 = 0.f;
#pragma unroll
    for (int j = 0; j < 8; j++) {
        int cj = ng * 64 + j * 8 + 2 * tg;
        float asx = asrc[cj], asy = asrc[cj + 1];
        float adx = adst[cj], ady = adst[cj + 1];
        ps0 += accA[j][0] * asx + accA[j][1] * asy;
        pd0 += accA[j][0] * adx + accA[j][1] * ady;
        ps1 += accA[j][2] * asx + accA[j][3] * asy;
        pd1 += accA[j][2] * adx + accA[j][3] * ady;
        ps2 += accB[j][0] * asx + accB[j][1] * asy;
        pd2 += accB[j][0] * adx + accB[j][1] * ady;
        ps3 += accB[j][2] * asx + accB[j][3] * asy;
        pd3 += accB[j][2] * adx + accB[j][3] * ady;
        int row;
        row = n0 + r0;
        if (row < NN) *(__half2*)&g_hh[row * 128 + cj] = __floats2half2_rn(accA[j][0], accA[j][1]);
        row = n0 + r0 + 8;
        if (row < NN) *(__half2*)&g_hh[row * 128 + cj] = __floats2half2_rn(accA[j][2], accA[j][3]);
        row = n0 + r0 + 16;
        if (row < NN) *(__half2*)&g_hh[row * 128 + cj] = __floats2half2_rn(accB[j][0], accB[j][1]);
        row = n0 + r0 + 24;
        if (row < NN) *(__half2*)&g_hh[row * 128 + cj] = __floats2half2_rn(accB[j][2], accB[j][3]);
    }
#pragma unroll
    for (int off = 1; off <= 2; off <<= 1) {
        ps0 += __shfl_xor_sync(0xffffffffu, ps0, off);
        ps1 += __shfl_xor_sync(0xffffffffu, ps1, off);
        ps2 += __shfl_xor_sync(0xffffffffu, ps2, off);
        ps3 += __shfl_xor_sync(0xffffffffu, ps3, off);
        pd0 += __shfl_xor_sync(0xffffffffu, pd0, off);
        pd1 += __shfl_xor_sync(0xffffffffu, pd1, off);
        pd2 += __shfl_xor_sync(0xffffffffu, pd2, off);
        pd3 += __shfl_xor_sync(0xffffffffu, pd3, off);
    }
    if (tg == 0) {
        int row;
        row = n0 + r0;
        if (row < NN) { g_als[row * 2 + ng] = ps0; g_ald[row * 2 + ng] = pd0; }
        row = n0 + r0 + 8;
        if (row < NN) { g_als[row * 2 + ng] = ps1; g_ald[row * 2 + ng] = pd1; }
        row = n0 + r0 + 16;
        if (row < NN) { g_als[row * 2 + ng] = ps2; g_ald[row * 2 + ng] = pd2; }
        row = n0 + r0 + 24;
        if (row < NN) { g_als[row * 2 + ng] = ps3; g_ald[row * 2 + ng] = pd3; }
    }
}

// ---------------- aggregation core (warp per dst node) ------------------------
__device__ __forceinline__ void aggr_node(int node, int lane, int hd, int c,
                                          float& a0, float& a1, float& a2,
                                          float& a3, float& den) {
    int beg = g_off[node], end = g_off[node + 1];
    float2 aldv = *(const float2*)&g_ald[node * 2];

    for (int base = beg; base < end; base += 32) {
        int idx = base + lane;
        int s = 0; float w0 = 0.f, w1 = 0.f;
        if (idx < end) {
            s = g_srcs[idx];
            float2 al = *(const float2*)&g_als[s * 2];
            float e0 = al.x + aldv.x; e0 = (e0 > 0.f) ? e0 : SLOPE * e0;
            float e1 = al.y + aldv.y; e1 = (e1 > 0.f) ? e1 : SLOPE * e1;
            w0 = __expf(e0); w1 = __expf(e1);
        }
        int cnt = min(32, end - base);
#pragma unroll 8
        for (int j = 0; j < 32; j++) {
            if (j >= cnt) break;
            int sj = __shfl_sync(0xffffffffu, s, j);
            float u0 = __shfl_sync(0xffffffffu, w0, j);
            float u1 = __shfl_sync(0xffffffffu, w1, j);
            float wg = hd ? u1 : u0;
            uint2 u = *(const uint2*)&g_hh[sj * 128 + c];
            float2 f0 = __half22float2(*(__half2*)&u.x);
            float2 f1 = __half22float2(*(__half2*)&u.y);
            a0 += wg * f0.x; a1 += wg * f0.y;
            a2 += wg * f1.x; a3 += wg * f1.y;
            den += wg;
        }
    }
}

// ---------------- fused aggregation (layers 0/1) + BN stats -------------------
__global__ void __launch_bounds__(256) k_aggr(const float* __restrict__ b,
                                              int statbuf) {
    __shared__ float ssum[FF], ssq[FF];
    int t = threadIdx.x, lane = t & 31, w = t >> 5;
    if (t < FF) { ssum[t] = 0.f; ssq[t] = 0.f; }
    __syncthreads();

    int node = blockIdx.x * 8 + w;
    int c = lane * 4;
    float v0 = 0.f, v1 = 0.f, v2 = 0.f, v3 = 0.f;
    if (node < NN) {
        int hd = lane >> 4;
        float a0 = 0.f, a1 = 0.f, a2 = 0.f, a3 = 0.f, den = 0.f;
        aggr_node(node, lane, hd, c, a0, a1, a2, a3, den);
        float inv = 1.f / (den + 1e-16f);
        float4 bb = *(const float4*)&b[c];
        v0 = a0 * inv + bb.x;
        v1 = a1 * inv + bb.y;
        v2 = a2 * inv + bb.z;
        v3 = a3 * inv + bb.w;
        *(float4*)&g_act[node * 128 + c] = make_float4(v0, v1, v2, v3);
    }
    atomicAdd(&ssum[c + 0], v0); atomicAdd(&ssq[c + 0], v0 * v0);
    atomicAdd(&ssum[c + 1], v1); atomicAdd(&ssq[c + 1], v1 * v1);
    atomicAdd(&ssum[c + 2], v2); atomicAdd(&ssq[c + 2], v2 * v2);
    atomicAdd(&ssum[c + 3], v3); atomicAdd(&ssq[c + 3], v3 * v3);
    __syncthreads();
    if (t < FF) {
        atomicAdd(&g_sumA[statbuf][t], ssum[t]);
        atomicAdd(&g_sqA[statbuf][t], ssq[t]);
    }
}

// ---------------- fused aggregation (layer 2): head-mean output ---------------
__global__ void __launch_bounds__(256) k_aggr_out(const float* __restrict__ b2,
                                                  float* __restrict__ out) {
    int t = threadIdx.x, lane = t & 31, w = t >> 5;
    int node = blockIdx.x * 8 + w;
    if (node >= NN) return;
    int c = lane * 4;
    int hd = lane >> 4;
    float a0 = 0.f, a1 = 0.f, a2 = 0.f, a3 = 0.f, den = 0.f;
    aggr_node(node, lane, hd, c, a0, a1, a2, a3, den);
    float inv = 1.f / (den + 1e-16f);
    float r0 = a0 * inv, r1 = a1 * inv, r2 = a2 * inv, r3 = a3 * inv;
    r0 = 0.5f * (r0 + __shfl_xor_sync(0xffffffffu, r0, 16));
    r1 = 0.5f * (r1 + __shfl_xor_sync(0xffffffffu, r1, 16));
    r2 = 0.5f * (r2 + __shfl_xor_sync(0xffffffffu, r2, 16));
    r3 = 0.5f * (r3 + __shfl_xor_sync(0xffffffffu, r3, 16));
    if (lane < 16) {
        float4 bb = *(const float4*)&b2[c];
        *(float4*)&out[node * 64 + c] =
            make_float4(r0 + bb.x, r1 + bb.y, r2 + bb.z, r3 + bb.w);
    }
}

// ---------------- launch -----------------------------------------------------
extern "C" void kernel_launch(void* const* d_in, const int* in_sizes, int n_in,
                              void* d_out, int out_size) {
    (void)in_sizes; (void)n_in; (void)out_size;
    const float* x      = (const float*)d_in[0];
    const void*  ei     = d_in[1];
    const float* W0  = (const float*)d_in[2];
    const float* as0 = (const float*)d_in[3];
    const float* ad0 = (const float*)d_in[4];
    const float* b0  = (const float*)d_in[5];
    const float* g0  = (const float*)d_in[6];
    const float* be0 = (const float*)d_in[7];
    const float* W1  = (const float*)d_in[8];
    const float* as1 = (const float*)d_in[9];
    const float* ad1 = (const float*)d_in[10];
    const float* b1  = (const float*)d_in[11];
    const float* g1  = (const float*)d_in[12];
    const float* be1 = (const float*)d_in[13];
    const float* W2  = (const float*)d_in[14];
    const float* as2 = (const float*)d_in[15];
    const float* ad2 = (const float*)d_in[16];
    const float* b2  = (const float*)d_in[17];
    float* out = (float*)d_out;

    cudaFuncSetAttribute(k_gemm, cudaFuncAttributeMaxDynamicSharedMemorySize,
                         GEMM_SMEM);

    const int GB  = (NN + 127) / 128;
    const int NB  = (NN + 255) / 256;
    const int EB  = (ET + 255) / 256;
    const int AB  = (NN + 7) / 8;

    // fork-join: CSR build runs concurrently with layer-0 GEMM
    cudaStream_t side;
    cudaStreamCreateWithFlags(&side, cudaStreamNonBlocking);
    cudaEvent_t evF, evJ;
    cudaEventCreateWithFlags(&evF, cudaEventDisableTiming);
    cudaEventCreateWithFlags(&evJ, cudaEventDisableTiming);

    cudaEventRecord(evF, 0);
    cudaStreamWaitEvent(side, evF, 0);

    // ---- CSR build (side stream) ----
    k_detect<<<NB, 256, 0, side>>>((const int*)ei);
    k_hist<<<EB, 256, 0, side>>>(ei);
    k_scanA<<<NB1024, 1024, 0, side>>>();
    k_scanC<<<NB, 256, 0, side>>>();
    k_scatter<<<EB, 256, 0, side>>>(ei);
    cudaEventRecord(evJ, side);

    // ---- layer 0 GEMM (default stream, concurrent with CSR) ----
    k_gemm<<<GB, 256, GEMM_SMEM>>>(x, W0, as0, ad0, nullptr, nullptr, -1);

    cudaStreamWaitEvent(0, evJ, 0);

    // ---- layer 0 aggregation ----
    k_aggr<<<AB, 256>>>(b0, 0);

    // ---- layer 1 (BN0 fused into A-load) ----
    k_gemm<<<GB, 256, GEMM_SMEM>>>(nullptr, W1, as1, ad1, g0, be0, 0);
    k_aggr<<<AB, 256>>>(b1, 1);

    // ---- layer 2 (BN1 fused into A-load, head-mean out) ----
    k_gemm<<<GB, 256, GEMM_SMEM>>>(nullptr, W2, as2, ad2, g1, be1, 1);
    k_aggr_out<<<AB, 256>>>(b2, out);

    cudaEventDestroy(evF);
    cudaEventDestroy(evJ);
    cudaStreamDestroy(side);
}